// round 3
// baseline (speedup 1.0000x reference)
#include <cuda_runtime.h>
#include <cuda_fp16.h>
#include <cstdint>

#define VOCABSZ 32000
#define EMBD    1024
#define HID     1024
#define G4      4096
#define NB      64
#define LSEQ    512
#define NCTA    128

// ---------------- device scratch (static; no cudaMalloc allowed) ----------------
__device__ __half g_Eb[(size_t)VOCABSZ * EMBD];          // E as fp16 (64 MB)
__device__ __half g_Bx[(size_t)G4 * 1024];               // W_x^T, [colp][k], gate-permuted (8 MB)
__device__ float  g_bias[G4];                            // permuted bias
__device__ float  g_Gx[(size_t)LSEQ * G4 * NB];          // precomputed x-gates, [t][cta][n][loc]
__device__ __half g_Hbuf[2][NB * HID];                   // H double buffer (fp16)
__device__ int    g_flags[NCTA];                         // per-CTA progress flags (monotonic)

// gate-column permutation: colp = cta*32 + loc ; loc>>3 = gate (i,f,o,g), loc&7 = unit-in-cta
__device__ __forceinline__ int perm_row(int colp) {
    int cta = colp >> 5, loc = colp & 31;
    return ((loc >> 3) << 10) + (cta << 3) + (loc & 7);
}

// ---------------- mma / ldmatrix / cp.async helpers -----------------------------
__device__ __forceinline__ unsigned smem_u32(const void* p) {
    return (unsigned)__cvta_generic_to_shared(p);
}
__device__ __forceinline__ void ldmatrix_x4(unsigned* r, unsigned addr) {
    asm volatile("ldmatrix.sync.aligned.m8n8.x4.shared.b16 {%0,%1,%2,%3}, [%4];"
                 : "=r"(r[0]), "=r"(r[1]), "=r"(r[2]), "=r"(r[3]) : "r"(addr));
}
__device__ __forceinline__ void ldmatrix_x2(unsigned* r, unsigned addr) {
    asm volatile("ldmatrix.sync.aligned.m8n8.x2.shared.b16 {%0,%1}, [%2];"
                 : "=r"(r[0]), "=r"(r[1]) : "r"(addr));
}
__device__ __forceinline__ void mma16816(float* d, const unsigned* a, unsigned b0, unsigned b1) {
    asm volatile("mma.sync.aligned.m16n8k16.row.col.f32.f16.f16.f32 "
                 "{%0,%1,%2,%3}, {%4,%5,%6,%7}, {%8,%9}, {%0,%1,%2,%3};"
                 : "+f"(d[0]), "+f"(d[1]), "+f"(d[2]), "+f"(d[3])
                 : "r"(a[0]), "r"(a[1]), "r"(a[2]), "r"(a[3]), "r"(b0), "r"(b1));
}
__device__ __forceinline__ void cp16(void* s, const void* g) {
    asm volatile("cp.async.cg.shared.global [%0], [%1], 16;"
                 :: "r"(smem_u32(s)), "l"(g) : "memory");
}
__device__ __forceinline__ void cp_commit() { asm volatile("cp.async.commit_group;" ::: "memory"); }
template <int N>
__device__ __forceinline__ void cp_wait() { asm volatile("cp.async.wait_group %0;" :: "n"(N) : "memory"); }

__device__ __forceinline__ void st_release(int* p, int v) {
    asm volatile("st.global.release.gpu.b32 [%0], %1;" :: "l"(p), "r"(v) : "memory");
}
__device__ __forceinline__ int ld_acquire(const int* p) {
    int v;
    asm volatile("ld.global.acquire.gpu.b32 %0, [%1];" : "=r"(v) : "l"(p) : "memory");
    return v;
}
__device__ __forceinline__ float sigf(float x) { return 1.0f / (1.0f + expf(-x)); }

// ---------------- prep: E -> fp16 ------------------------------------------------
__global__ __launch_bounds__(256) void k_cvt_e(const float* __restrict__ E) {
    size_t total8 = (size_t)VOCABSZ * EMBD / 8;
    size_t stride = (size_t)gridDim.x * blockDim.x;
    for (size_t i = (size_t)blockIdx.x * blockDim.x + threadIdx.x; i < total8; i += stride) {
        const float4* s = (const float4*)(E + i * 8);
        float4 v0 = s[0], v1 = s[1];
        __half2 h0 = __floats2half2_rn(v0.x, v0.y);
        __half2 h1 = __floats2half2_rn(v0.z, v0.w);
        __half2 h2 = __floats2half2_rn(v1.x, v1.y);
        __half2 h3 = __floats2half2_rn(v1.z, v1.w);
        uint4 o;
        o.x = *(unsigned*)&h0; o.y = *(unsigned*)&h1;
        o.z = *(unsigned*)&h2; o.w = *(unsigned*)&h3;
        ((uint4*)g_Eb)[i] = o;
    }
}

// ---------------- prep: pack Bx, bias, reset flags & H0 --------------------------
__global__ __launch_bounds__(256) void k_pack(const float* __restrict__ W,
                                              const float* __restrict__ Wb) {
    int i0 = blockIdx.x * blockDim.x + threadIdx.x;
    int stride = gridDim.x * blockDim.x;
    for (int idx = i0; idx < G4 * 1024; idx += stride) {
        int colp = idx >> 10, k = idx & 1023;
        g_Bx[idx] = __float2half(W[(size_t)perm_row(colp) * 2048 + 1024 + k]);
    }
    for (int idx = i0; idx < G4; idx += stride) g_bias[idx] = Wb[perm_row(idx)];
    for (int idx = i0; idx < NCTA; idx += stride) g_flags[idx] = 0;
    for (int idx = i0; idx < NB * HID; idx += stride) g_Hbuf[0][idx] = __float2half(0.0f);
}

// ---------------- phase 1: Gx = embed(X) @ Wx^T + b ------------------------------
// CTA tile 128(m) x 128(n), K-chunk 64, cp.async double buffered.
// 8 warps: wm 0..3 (32 rows), wn 0..1 (64 cols).
#define GX_KC   64
#define GX_NKC  (1024 / GX_KC)
#define GX_STR  72                           // halves per row (64 + 8 pad)
#define GX_TILE (128 * GX_STR)               // halves per buffer tile
#define GX_SMEM (4 * GX_TILE * 2)            // As[2] + Bs[2], bytes

__global__ __launch_bounds__(256) void k_gx(const int* __restrict__ X) {
    extern __shared__ __align__(16) __half dsm[];
    __half* As = dsm;                        // [2][128][GX_STR]
    __half* Bs = dsm + 2 * GX_TILE;          // [2][128][GX_STR]
    __shared__ int   toks[128];
    __shared__ float bsm[128];

    int tid = threadIdx.x, lane = tid & 31, warp = tid >> 5;
    int wm = warp >> 1, wn = warp & 1;
    int mblk = blockIdx.y * 128, nblk = blockIdx.x * 128;

    if (tid < 128) {
        int m = mblk + tid;                  // m = t*64 + n
        toks[tid] = X[(m & 63) * LSEQ + (m >> 6)];
        bsm[tid] = g_bias[nblk + tid];
    }
    __syncthreads();

    // chunk loader: 128 rows x 64 halves per matrix, 16B per cp, 4 per thread each
    auto issue = [&](int c) {
        int buf = c & 1, k0 = c * GX_KC;
#pragma unroll
        for (int i = 0; i < 4; ++i) {
            int idx = tid + i * 256;         // 0..1023
            int row = idx >> 3, q = idx & 7;
            cp16(&As[buf * GX_TILE + row * GX_STR + q * 8],
                 &g_Eb[(size_t)toks[row] * EMBD + k0 + q * 8]);
        }
#pragma unroll
        for (int i = 0; i < 4; ++i) {
            int idx = tid + i * 256;
            int row = idx >> 3, q = idx & 7;
            cp16(&Bs[buf * GX_TILE + row * GX_STR + q * 8],
                 &g_Bx[(size_t)(nblk + row) * 1024 + k0 + q * 8]);
        }
        cp_commit();
    };

    float acc[2][8][4];
#pragma unroll
    for (int a = 0; a < 2; ++a)
#pragma unroll
        for (int b = 0; b < 8; ++b)
#pragma unroll
            for (int c = 0; c < 4; ++c) acc[a][b][c] = 0.0f;

    issue(0);
    for (int c = 0; c < GX_NKC; ++c) {
        if (c + 1 < GX_NKC) { issue(c + 1); cp_wait<1>(); }
        else cp_wait<0>();
        __syncthreads();
        const __half* Ab = As + (c & 1) * GX_TILE;
        const __half* Bb = Bs + (c & 1) * GX_TILE;
#pragma unroll
        for (int ks = 0; ks < GX_KC / 16; ++ks) {
            unsigned a[2][4];
#pragma unroll
            for (int mt = 0; mt < 2; ++mt)
                ldmatrix_x4(a[mt], smem_u32(Ab + (wm * 32 + mt * 16 + (lane & 15)) * GX_STR
                                               + ks * 16 + (lane >> 4) * 8));
#pragma unroll
            for (int nt = 0; nt < 8; ++nt) {
                unsigned b[2];
                ldmatrix_x2(b, smem_u32(Bb + (wn * 64 + nt * 8 + (lane & 7)) * GX_STR
                                           + ks * 16 + ((lane >> 3) & 1) * 8));
                mma16816(acc[0][nt], a[0], b[0], b[1]);
                mma16816(acc[1][nt], a[1], b[0], b[1]);
            }
        }
        __syncthreads();   // protect buffer (c&1) before issue(c+2) overwrites it
    }

    // epilogue: add bias, store permuted Gx[t][cta][n][loc]
#pragma unroll
    for (int mt = 0; mt < 2; ++mt) {
#pragma unroll
        for (int nt = 0; nt < 8; ++nt) {
            int mrow = mblk + wm * 32 + mt * 16 + (lane >> 2);
            int cloc = wn * 64 + nt * 8 + ((lane & 3) << 1);
            int colp = nblk + cloc;
            float b0 = bsm[cloc], b1 = bsm[cloc + 1];
            const float* c = acc[mt][nt];
#pragma unroll
            for (int rr = 0; rr < 2; ++rr) {
                int m = mrow + rr * 8;
                int t = m >> 6, n = m & 63;
                size_t off = (((size_t)t * NCTA + (colp >> 5)) * NB + n) * 32 + (colp & 31);
                float2 v; v.x = c[rr * 2] + b0; v.y = c[rr * 2 + 1] + b1;
                *(float2*)&g_Gx[off] = v;
            }
        }
    }
}

// ---------------- phase 2: persistent recurrent kernel ---------------------------
// 128 CTAs x 256 threads, each CTA owns 8 hidden units (32 gate columns).
#define HS_STRIDE 1032
#define SM_HS 0
#define SM_WS (64 * HS_STRIDE * 2)
#define SM_GT (SM_WS + 32 * HS_STRIDE * 2)
#define SM_C  (SM_GT + 64 * 32 * 4)
#define SM_GX (SM_C + 512 * 4)
#define SMEM_REC (SM_GX + 2048 * 4)

__global__ void __launch_bounds__(256, 1) k_rec(const float* __restrict__ W,
                                                float* __restrict__ out) {
    extern __shared__ __align__(16) char smem[];
    __half (*Hs)[HS_STRIDE] = (__half(*)[HS_STRIDE])(smem + SM_HS);
    __half (*Ws)[HS_STRIDE] = (__half(*)[HS_STRIDE])(smem + SM_WS);
    float (*gsm)[32]        = (float(*)[32])(smem + SM_GT);
    float* Cs               = (float*)(smem + SM_C);
    float* gxs              = (float*)(smem + SM_GX);

    int cta = blockIdx.x;
    int tid = threadIdx.x, lane = tid & 31, warp = tid >> 5;
    int wm = warp & 3, wn = warp >> 2;   // wm: m-tile 0..3 (16 rows), wn: 0..1 (16 gate cols)

    // resident weight slice: Ws[nloc][k] = W[perm(cta*32+nloc)][k]  (h-part)
    for (int idx = tid; idx < 32 * 1024; idx += 256) {
        int nloc = idx >> 10, k = idx & 1023;
        int wrow = ((nloc >> 3) << 10) + (cta << 3) + (nloc & 7);
        Ws[nloc][k] = __float2half(W[(size_t)wrow * 2048 + k]);
    }
    for (int idx = tid; idx < 512; idx += 256) Cs[idx] = 0.0f;
    __syncthreads();

    for (int t = 0; t < LSEQ; ++t) {
        // prefetch this step's Gx slice (precomputed; independent of barrier)
        const float* gx = g_Gx + ((size_t)t * NCTA + cta) * NB * 32;
#pragma unroll
        for (int i = 0; i < 2; ++i) {
            int idx = tid + i * 256;
            cp16(&gxs[idx * 4], gx + idx * 4);
        }
        cp_commit();

        // atomic-free grid barrier: wait until all CTAs finished step t-1
        if (warp == 0) {
            const int* f = &g_flags[lane * 4];
            bool ok;
            do {
                int f0 = ld_acquire(f + 0), f1 = ld_acquire(f + 1);
                int f2 = ld_acquire(f + 2), f3 = ld_acquire(f + 3);
                ok = (f0 >= t) && (f1 >= t) && (f2 >= t) && (f3 >= t);
            } while (__ballot_sync(0xffffffffu, ok) != 0xffffffffu);
        }
        __syncthreads();

        // stage H (two 64KB halves; half1 overlaps half0 compute)
        const __half* Hg = g_Hbuf[t & 1];
#pragma unroll
        for (int h = 0; h < 2; ++h) {
#pragma unroll
            for (int i = 0; i < 16; ++i) {
                int idx = tid + i * 256;          // 0..4095
                int row = idx >> 6, c16 = idx & 63;
                cp16(&Hs[row][h * 512 + c16 * 8], Hg + row * 1024 + h * 512 + c16 * 8);
            }
            cp_commit();
        }

        float acc0[4] = {0, 0, 0, 0}, acc1[4] = {0, 0, 0, 0};

        cp_wait<1>();        // gx + H-half0 complete
        __syncthreads();
#pragma unroll 8
        for (int kt = 0; kt < 32; ++kt) {
            unsigned a[4], b0[2], b1[2];
            ldmatrix_x4(a, smem_u32(&Hs[wm * 16 + (lane & 15)][kt * 16 + (lane >> 4) * 8]));
            ldmatrix_x2(b0, smem_u32(&Ws[wn * 16 + (lane & 7)][kt * 16 + ((lane >> 3) & 1) * 8]));
            ldmatrix_x2(b1, smem_u32(&Ws[wn * 16 + 8 + (lane & 7)][kt * 16 + ((lane >> 3) & 1) * 8]));
            mma16816(acc0, a, b0[0], b0[1]);
            mma16816(acc1, a, b1[0], b1[1]);
        }
        cp_wait<0>();        // H-half1 complete
        __syncthreads();
#pragma unroll 8
        for (int kt = 32; kt < 64; ++kt) {
            unsigned a[4], b0[2], b1[2];
            ldmatrix_x4(a, smem_u32(&Hs[wm * 16 + (lane & 15)][kt * 16 + (lane >> 4) * 8]));
            ldmatrix_x2(b0, smem_u32(&Ws[wn * 16 + (lane & 7)][kt * 16 + ((lane >> 3) & 1) * 8]));
            ldmatrix_x2(b1, smem_u32(&Ws[wn * 16 + 8 + (lane & 7)][kt * 16 + ((lane >> 3) & 1) * 8]));
            mma16816(acc0, a, b0[0], b0[1]);
            mma16816(acc1, a, b1[0], b1[1]);
        }

        // write gates to SMEM exchange buffer
        {
            int m = wm * 16 + (lane >> 2);
            int cl = wn * 16 + ((lane & 3) << 1);
            gsm[m][cl] = acc0[0];         gsm[m][cl + 1] = acc0[1];
            gsm[m + 8][cl] = acc0[2];     gsm[m + 8][cl + 1] = acc0[3];
            gsm[m][cl + 8] = acc1[0];     gsm[m][cl + 9] = acc1[1];
            gsm[m + 8][cl + 8] = acc1[2]; gsm[m + 8][cl + 9] = acc1[3];
        }
        __syncthreads();

        // elementwise LSTM update for this CTA's 8 units x 64 batch
        __half* Hn = g_Hbuf[(t & 1) ^ 1];
#pragma unroll
        for (int p = tid; p < 512; p += 256) {
            int m = p >> 3, j = p & 7;
            float vi = gsm[m][j]      + gxs[m * 32 + j];
            float vf = gsm[m][8 + j]  + gxs[m * 32 + 8 + j];
            float vo = gsm[m][16 + j] + gxs[m * 32 + 16 + j];
            float vg = gsm[m][24 + j] + gxs[m * 32 + 24 + j];
            float ig = sigf(vi), fg = sigf(vf), og = sigf(vo), gg = tanhf(vg);
            float C = fg * Cs[p] + ig * gg;
            Cs[p] = C;
            float hval = og * tanhf(C);
            int col = (cta << 3) + j;
            Hn[m * 1024 + col] = __float2half(hval);
            if (t == LSEQ - 1) out[m * 1024 + col] = hval;
        }
        __syncthreads();

        // release: per-CTA flag, no atomics, no membar.gpu
        if (tid == 0) st_release(&g_flags[cta], t + 1);
    }
}

// ---------------- launch ----------------------------------------------------------
extern "C" void kernel_launch(void* const* d_in, const int* in_sizes, int n_in,
                              void* d_out, int out_size) {
    (void)in_sizes; (void)n_in; (void)out_size;
    const int*   X  = (const int*)d_in[0];
    const float* E  = (const float*)d_in[1];
    const float* W  = (const float*)d_in[2];
    const float* Wb = (const float*)d_in[3];
    float* out = (float*)d_out;

    cudaFuncSetAttribute(k_rec, cudaFuncAttributeMaxDynamicSharedMemorySize, SMEM_REC);
    cudaFuncSetAttribute(k_gx, cudaFuncAttributeMaxDynamicSharedMemorySize, GX_SMEM);

    k_cvt_e<<<2048, 256>>>(E);
    k_pack<<<1024, 256>>>(W, Wb);
    k_gx<<<dim3(32, 256), 256, GX_SMEM>>>(X);
    k_rec<<<NCTA, 256, SMEM_REC>>>(W, out);
}

// round 4
// speedup vs baseline: 1.3859x; 1.3859x over previous
#include <cuda_runtime.h>
#include <cuda_fp16.h>
#include <cstdint>

#define VOCABSZ 32000
#define EMBD    1024
#define HID     1024
#define G4      4096
#define NB      64
#define LSEQ    512
#define NCTA    128

// ---------------- device scratch (static; no cudaMalloc allowed) ----------------
__device__ __half g_Eb[(size_t)VOCABSZ * EMBD];          // E as fp16 (64 MB)
__device__ __half g_Bx[(size_t)G4 * 1024];               // W_x^T, [colp][k], gate-permuted (8 MB)
__device__ float  g_bias[G4];                            // permuted bias
__device__ float  g_Gx[(size_t)LSEQ * G4 * NB];          // precomputed x-gates, [t][cta][n][loc]
__device__ __half g_Hbuf[2][NB * HID];                   // H double buffer (fp16)
__device__ int    g_bar[LSEQ];                           // per-step grid-barrier counters

// gate-column permutation: colp = cta*32 + loc ; loc>>3 = gate (i,f,o,g), loc&7 = unit-in-cta
__device__ __forceinline__ int perm_row(int colp) {
    int cta = colp >> 5, loc = colp & 31;
    return ((loc >> 3) << 10) + (cta << 3) + (loc & 7);
}

// ---------------- mma / ldmatrix / cp.async helpers -----------------------------
__device__ __forceinline__ unsigned smem_u32(const void* p) {
    return (unsigned)__cvta_generic_to_shared(p);
}
__device__ __forceinline__ void ldmatrix_x4(unsigned* r, unsigned addr) {
    asm volatile("ldmatrix.sync.aligned.m8n8.x4.shared.b16 {%0,%1,%2,%3}, [%4];"
                 : "=r"(r[0]), "=r"(r[1]), "=r"(r[2]), "=r"(r[3]) : "r"(addr));
}
__device__ __forceinline__ void ldmatrix_x2(unsigned* r, unsigned addr) {
    asm volatile("ldmatrix.sync.aligned.m8n8.x2.shared.b16 {%0,%1}, [%2];"
                 : "=r"(r[0]), "=r"(r[1]) : "r"(addr));
}
__device__ __forceinline__ void mma16816(float* d, const unsigned* a, unsigned b0, unsigned b1) {
    asm volatile("mma.sync.aligned.m16n8k16.row.col.f32.f16.f16.f32 "
                 "{%0,%1,%2,%3}, {%4,%5,%6,%7}, {%8,%9}, {%0,%1,%2,%3};"
                 : "+f"(d[0]), "+f"(d[1]), "+f"(d[2]), "+f"(d[3])
                 : "r"(a[0]), "r"(a[1]), "r"(a[2]), "r"(a[3]), "r"(b0), "r"(b1));
}
__device__ __forceinline__ void cp16(void* s, const void* g) {
    asm volatile("cp.async.cg.shared.global [%0], [%1], 16;"
                 :: "r"(smem_u32(s)), "l"(g) : "memory");
}
__device__ __forceinline__ void cp_commit() { asm volatile("cp.async.commit_group;" ::: "memory"); }
template <int N>
__device__ __forceinline__ void cp_wait() { asm volatile("cp.async.wait_group %0;" :: "n"(N) : "memory"); }

__device__ __forceinline__ float sigf(float x) { return 1.0f / (1.0f + expf(-x)); }

// ---------------- prep: E -> fp16 ------------------------------------------------
__global__ __launch_bounds__(256) void k_cvt_e(const float* __restrict__ E) {
    size_t total8 = (size_t)VOCABSZ * EMBD / 8;
    size_t stride = (size_t)gridDim.x * blockDim.x;
    for (size_t i = (size_t)blockIdx.x * blockDim.x + threadIdx.x; i < total8; i += stride) {
        const float4* s = (const float4*)(E + i * 8);
        float4 v0 = s[0], v1 = s[1];
        __half2 h0 = __floats2half2_rn(v0.x, v0.y);
        __half2 h1 = __floats2half2_rn(v0.z, v0.w);
        __half2 h2 = __floats2half2_rn(v1.x, v1.y);
        __half2 h3 = __floats2half2_rn(v1.z, v1.w);
        uint4 o;
        o.x = *(unsigned*)&h0; o.y = *(unsigned*)&h1;
        o.z = *(unsigned*)&h2; o.w = *(unsigned*)&h3;
        ((uint4*)g_Eb)[i] = o;
    }
}

// ---------------- prep: pack Bx, bias, reset barriers & H0 -----------------------
__global__ __launch_bounds__(256) void k_pack(const float* __restrict__ W,
                                              const float* __restrict__ Wb) {
    int i0 = blockIdx.x * blockDim.x + threadIdx.x;
    int stride = gridDim.x * blockDim.x;
    for (int idx = i0; idx < G4 * 1024; idx += stride) {
        int colp = idx >> 10, k = idx & 1023;
        g_Bx[idx] = __float2half(W[(size_t)perm_row(colp) * 2048 + 1024 + k]);
    }
    for (int idx = i0; idx < G4; idx += stride) g_bias[idx] = Wb[perm_row(idx)];
    for (int idx = i0; idx < LSEQ; idx += stride) g_bar[idx] = 0;
    for (int idx = i0; idx < NB * HID; idx += stride) g_Hbuf[0][idx] = __float2half(0.0f);
}

// ---------------- phase 1: Gx = embed(X) @ Wx^T + b  (R2-proven version) ---------
__global__ __launch_bounds__(256) void k_gx(const int* __restrict__ X) {
    __shared__ __align__(16) __half As[128][40];
    __shared__ __align__(16) __half Bs[128][40];
    __shared__ int   toks[128];
    __shared__ float bsm[128];

    int tid = threadIdx.x, lane = tid & 31, warp = tid >> 5;
    int wm = warp >> 1, wn = warp & 1;
    int mblk = blockIdx.y * 128, nblk = blockIdx.x * 128;

    if (tid < 128) {
        int m = mblk + tid;                      // m = t*64 + n
        toks[tid] = X[(m & 63) * LSEQ + (m >> 6)];
        bsm[tid] = g_bias[nblk + tid];
    }

    float acc[2][8][4];
#pragma unroll
    for (int a = 0; a < 2; ++a)
#pragma unroll
        for (int b = 0; b < 8; ++b)
#pragma unroll
            for (int c = 0; c < 4; ++c) acc[a][b][c] = 0.0f;

    for (int kc = 0; kc < 32; ++kc) {
        int k0 = kc * 32;
        __syncthreads();
#pragma unroll
        for (int r = 0; r < 2; ++r) {
            int idx = tid + r * 256;
            int row = idx >> 2, q = idx & 3;
            *(uint4*)&As[row][q * 8] =
                *(const uint4*)&g_Eb[(size_t)toks[row] * EMBD + k0 + q * 8];
        }
#pragma unroll
        for (int r = 0; r < 2; ++r) {
            int idx = tid + r * 256;
            int row = idx >> 2, q = idx & 3;
            *(uint4*)&Bs[row][q * 8] =
                *(const uint4*)&g_Bx[(size_t)(nblk + row) * 1024 + k0 + q * 8];
        }
        __syncthreads();
#pragma unroll
        for (int ks = 0; ks < 2; ++ks) {
            unsigned a[2][4];
#pragma unroll
            for (int mt = 0; mt < 2; ++mt)
                ldmatrix_x4(a[mt], smem_u32(&As[wm * 32 + mt * 16 + (lane & 15)]
                                              [ks * 16 + (lane >> 4) * 8]));
#pragma unroll
            for (int nt = 0; nt < 8; ++nt) {
                unsigned b[2];
                ldmatrix_x2(b, smem_u32(&Bs[wn * 64 + nt * 8 + (lane & 7)]
                                          [ks * 16 + ((lane >> 3) & 1) * 8]));
                mma16816(acc[0][nt], a[0], b[0], b[1]);
                mma16816(acc[1][nt], a[1], b[0], b[1]);
            }
        }
    }

#pragma unroll
    for (int mt = 0; mt < 2; ++mt) {
#pragma unroll
        for (int nt = 0; nt < 8; ++nt) {
            int mrow = mblk + wm * 32 + mt * 16 + (lane >> 2);
            int cloc = wn * 64 + nt * 8 + ((lane & 3) << 1);
            int colp = nblk + cloc;
            float b0 = bsm[cloc], b1 = bsm[cloc + 1];
            const float* c = acc[mt][nt];
#pragma unroll
            for (int rr = 0; rr < 2; ++rr) {
                int m = mrow + rr * 8;
                int t = m >> 6, n = m & 63;
                size_t off = (((size_t)t * NCTA + (colp >> 5)) * NB + n) * 32 + (colp & 31);
                float2 v; v.x = c[rr * 2] + b0; v.y = c[rr * 2 + 1] + b1;
                *(float2*)&g_Gx[off] = v;
            }
        }
    }
}

// ---------------- phase 2: persistent recurrent kernel ---------------------------
// 128 CTAs x 256 threads, each CTA owns 8 hidden units (32 gate columns).
// Warp split (m_w=2, n_w=1, k_w=4): warp (wm2, wk) computes batch rows
// [wm2*32, +32) x all 32 gate cols over K quarter [wk*256, +256).
// Each warp's H slice is warp-private -> per-warp cp.async pipeline, no CTA syncs.
// K-partials reduced through gsm[4][64][33] which ALIASES the dead Hs region.
#define HS_STRIDE 1032
#define SM_HS 0
#define SM_WS (64 * HS_STRIDE * 2)                 // 132096
#define SMEM_REC (SM_WS + 32 * HS_STRIDE * 2)      // 198144

__global__ void __launch_bounds__(256, 1) k_rec(const float* __restrict__ W,
                                                float* __restrict__ out) {
    extern __shared__ __align__(16) char smem[];
    __half (*Hs)[HS_STRIDE] = (__half(*)[HS_STRIDE])(smem + SM_HS);
    __half (*Ws)[HS_STRIDE] = (__half(*)[HS_STRIDE])(smem + SM_WS);
    float* gsm = (float*)(smem + SM_HS);           // [4][64][33], aliases Hs (time-disjoint)

    int cta = blockIdx.x;
    int tid = threadIdx.x, lane = tid & 31, warp = tid >> 5;
    int wm2 = warp & 1;          // m-half: batch rows [wm2*32, +32)
    int wk  = warp >> 1;         // k-quarter: [wk*256, +256)
    int rb  = wm2 * 32;          // row base
    int cb  = wk * 256;          // col base (K)

    // resident weight slice: Ws[nloc][k] = W[perm(cta*32+nloc)][k]  (h-part)
    for (int idx = tid; idx < 32 * 1024; idx += 256) {
        int nloc = idx >> 10, k = idx & 1023;
        int wrow = ((nloc >> 3) << 10) + (cta << 3) + (nloc & 7);
        Ws[nloc][k] = __float2half(W[(size_t)wrow * 2048 + k]);
    }
    __syncthreads();

    // per-thread elementwise ownership (step-invariant): batch m, units j0, j0+1
    int em = tid >> 2, ej0 = (tid & 3) * 2;
    float C0 = 0.0f, C1 = 0.0f;
    const float* gxbase = g_Gx + (size_t)cta * NB * 32 + em * 32 + ej0;

    for (int t = 0; t < LSEQ; ++t) {
        // prefetch this step's 8 gx values into registers (plain LDG, pre-barrier OK)
        const float* gxp = gxbase + (size_t)t * G4 * NB;
        float2 gxr[4];
#pragma unroll
        for (int g = 0; g < 4; ++g) gxr[g] = *(const float2*)(gxp + g * 8);

        // stage this warp's private H slice (32 rows x 256 K) in 2 chunks of 128 K
        const __half* Hg = g_Hbuf[t & 1];
#pragma unroll
        for (int ch = 0; ch < 2; ++ch) {
#pragma unroll
            for (int i = 0; i < 16; ++i) {
                int idx = i * 32 + lane;          // 0..511
                int row = rb + (idx >> 4);
                int col = cb + ch * 128 + (idx & 15) * 8;
                cp16(&Hs[row][col], Hg + row * 1024 + col);
            }
            cp_commit();
        }

        float acc[2][4][4];
#pragma unroll
        for (int a = 0; a < 2; ++a)
#pragma unroll
            for (int b = 0; b < 4; ++b)
#pragma unroll
                for (int c = 0; c < 4; ++c) acc[a][b][c] = 0.0f;

        cp_wait<1>();
        __syncwarp();
#pragma unroll
        for (int half = 0; half < 2; ++half) {
#pragma unroll 4
            for (int kt = 0; kt < 8; ++kt) {
                int k0 = cb + half * 128 + kt * 16;
                unsigned a[2][4];
#pragma unroll
                for (int mt = 0; mt < 2; ++mt)
                    ldmatrix_x4(a[mt], smem_u32(&Hs[rb + mt * 16 + (lane & 15)]
                                                  [k0 + (lane >> 4) * 8]));
#pragma unroll
                for (int bg = 0; bg < 2; ++bg) {
                    unsigned b[4];
                    ldmatrix_x4(b, smem_u32(&Ws[bg * 16 + ((lane >> 4) << 3) + (lane & 7)]
                                              [k0 + ((lane >> 3) & 1) * 8]));
#pragma unroll
                    for (int mt = 0; mt < 2; ++mt) {
                        mma16816(acc[mt][bg * 2],     a[mt], b[0], b[1]);
                        mma16816(acc[mt][bg * 2 + 1], a[mt], b[2], b[3]);
                    }
                }
            }
            if (half == 0) { cp_wait<0>(); __syncwarp(); }
        }

        // all Hs reads done before gsm (alias) is written
        __syncthreads();
        {
            float* gp = gsm + wk * (64 * 33);
            int mrow = rb + (lane >> 2);
            int ncol = (lane & 3) << 1;
#pragma unroll
            for (int mt = 0; mt < 2; ++mt)
#pragma unroll
                for (int ng = 0; ng < 4; ++ng) {
                    const float* c = acc[mt][ng];
                    int m = mrow + mt * 16, n = ng * 8 + ncol;
                    gp[m * 33 + n]           = c[0];
                    gp[m * 33 + n + 1]       = c[1];
                    gp[(m + 8) * 33 + n]     = c[2];
                    gp[(m + 8) * 33 + n + 1] = c[3];
                }
        }
        __syncthreads();

        // elementwise: 4-way K-reduction + LSTM cell (C in registers)
        float s[4][2];
#pragma unroll
        for (int g = 0; g < 4; ++g) {
            float v0 = gxr[g].x, v1 = gxr[g].y;
            int base = em * 33 + g * 8 + ej0;
#pragma unroll
            for (int q = 0; q < 4; ++q) {
                v0 += gsm[q * (64 * 33) + base];
                v1 += gsm[q * (64 * 33) + base + 1];
            }
            s[g][0] = v0; s[g][1] = v1;
        }
        float i0 = sigf(s[0][0]), f0 = sigf(s[1][0]), o0 = sigf(s[2][0]), g0 = tanhf(s[3][0]);
        float i1 = sigf(s[0][1]), f1 = sigf(s[1][1]), o1 = sigf(s[2][1]), g1 = tanhf(s[3][1]);
        C0 = f0 * C0 + i0 * g0;
        C1 = f1 * C1 + i1 * g1;
        float h0 = o0 * tanhf(C0), h1 = o1 * tanhf(C1);

        __half* Hn = g_Hbuf[(t & 1) ^ 1];
        int hcol = (cta << 3) + ej0;
        *(__half2*)(Hn + em * 1024 + hcol) = __floats2half2_rn(h0, h1);
        if (t == LSEQ - 1) {
            float2 ov; ov.x = h0; ov.y = h1;
            *(float2*)(out + em * 1024 + hcol) = ov;
        }

        // grid barrier (R2-proven: single atomic counter + broadcast poll)
        __threadfence();
        __syncthreads();
        if (tid == 0) {
            atomicAdd(&g_bar[t], 1);
            while (*(volatile int*)&g_bar[t] < NCTA) { }
        }
        __syncthreads();
    }
}

// ---------------- launch ----------------------------------------------------------
extern "C" void kernel_launch(void* const* d_in, const int* in_sizes, int n_in,
                              void* d_out, int out_size) {
    (void)in_sizes; (void)n_in; (void)out_size;
    const int*   X  = (const int*)d_in[0];
    const float* E  = (const float*)d_in[1];
    const float* W  = (const float*)d_in[2];
    const float* Wb = (const float*)d_in[3];
    float* out = (float*)d_out;

    cudaFuncSetAttribute(k_rec, cudaFuncAttributeMaxDynamicSharedMemorySize, SMEM_REC);

    k_cvt_e<<<2048, 256>>>(E);
    k_pack<<<1024, 256>>>(W, Wb);
    k_gx<<<dim3(32, 256), 256>>>(X);
    k_rec<<<NCTA, 256, SMEM_REC>>>(W, out);
}

// round 5
// speedup vs baseline: 1.5432x; 1.1135x over previous
#include <cuda_runtime.h>
#include <cuda_fp16.h>
#include <cstdint>

#define VOCABSZ 32000
#define EMBD    1024
#define HID     1024
#define G4      4096
#define NB      64
#define LSEQ    512
#define NCTA    128

// ---------------- device scratch (static; no cudaMalloc allowed) ----------------
__device__ __half g_Eb[(size_t)VOCABSZ * EMBD];          // E as fp16 (64 MB)
__device__ __half g_Bx[(size_t)G4 * 1024];               // W_x^T, [colp][k], gate-permuted (8 MB)
__device__ float  g_bias[G4];                            // permuted bias
__device__ float  g_Gx[(size_t)LSEQ * G4 * NB];          // precomputed x-gates, [t][cta][n][loc]
__device__ __half g_Hbuf[2][NB * HID];                   // H double buffer (fp16)
__device__ int    g_bar[LSEQ];                           // per-step grid-barrier counters

// gate-column permutation: colp = cta*32 + loc ; loc>>3 = gate (i,f,o,g), loc&7 = unit-in-cta
__device__ __forceinline__ int perm_row(int colp) {
    int cta = colp >> 5, loc = colp & 31;
    return ((loc >> 3) << 10) + (cta << 3) + (loc & 7);
}

// ---------------- mma / ldmatrix / cp.async helpers -----------------------------
__device__ __forceinline__ unsigned smem_u32(const void* p) {
    return (unsigned)__cvta_generic_to_shared(p);
}
__device__ __forceinline__ void ldmatrix_x4(unsigned* r, unsigned addr) {
    asm volatile("ldmatrix.sync.aligned.m8n8.x4.shared.b16 {%0,%1,%2,%3}, [%4];"
                 : "=r"(r[0]), "=r"(r[1]), "=r"(r[2]), "=r"(r[3]) : "r"(addr));
}
__device__ __forceinline__ void ldmatrix_x2(unsigned* r, unsigned addr) {
    asm volatile("ldmatrix.sync.aligned.m8n8.x2.shared.b16 {%0,%1}, [%2];"
                 : "=r"(r[0]), "=r"(r[1]) : "r"(addr));
}
__device__ __forceinline__ void mma16816(float* d, const unsigned* a, unsigned b0, unsigned b1) {
    asm volatile("mma.sync.aligned.m16n8k16.row.col.f32.f16.f16.f32 "
                 "{%0,%1,%2,%3}, {%4,%5,%6,%7}, {%8,%9}, {%0,%1,%2,%3};"
                 : "+f"(d[0]), "+f"(d[1]), "+f"(d[2]), "+f"(d[3])
                 : "r"(a[0]), "r"(a[1]), "r"(a[2]), "r"(a[3]), "r"(b0), "r"(b1));
}
__device__ __forceinline__ void cp16(void* s, const void* g) {
    asm volatile("cp.async.cg.shared.global [%0], [%1], 16;"
                 :: "r"(smem_u32(s)), "l"(g) : "memory");
}
__device__ __forceinline__ void cp_commit() { asm volatile("cp.async.commit_group;" ::: "memory"); }
template <int N>
__device__ __forceinline__ void cp_wait() { asm volatile("cp.async.wait_group %0;" :: "n"(N) : "memory"); }

__device__ __forceinline__ float sigf(float x) { return 1.0f / (1.0f + expf(-x)); }

// ---------------- prep: E -> fp16 ------------------------------------------------
__global__ __launch_bounds__(256) void k_cvt_e(const float* __restrict__ E) {
    size_t total8 = (size_t)VOCABSZ * EMBD / 8;
    size_t stride = (size_t)gridDim.x * blockDim.x;
    for (size_t i = (size_t)blockIdx.x * blockDim.x + threadIdx.x; i < total8; i += stride) {
        const float4* s = (const float4*)(E + i * 8);
        float4 v0 = s[0], v1 = s[1];
        __half2 h0 = __floats2half2_rn(v0.x, v0.y);
        __half2 h1 = __floats2half2_rn(v0.z, v0.w);
        __half2 h2 = __floats2half2_rn(v1.x, v1.y);
        __half2 h3 = __floats2half2_rn(v1.z, v1.w);
        uint4 o;
        o.x = *(unsigned*)&h0; o.y = *(unsigned*)&h1;
        o.z = *(unsigned*)&h2; o.w = *(unsigned*)&h3;
        ((uint4*)g_Eb)[i] = o;
    }
}

// ---------------- prep: pack Bx, bias, reset barriers & H0 -----------------------
__global__ __launch_bounds__(256) void k_pack(const float* __restrict__ W,
                                              const float* __restrict__ Wb) {
    int i0 = blockIdx.x * blockDim.x + threadIdx.x;
    int stride = gridDim.x * blockDim.x;
    for (int idx = i0; idx < G4 * 1024; idx += stride) {
        int colp = idx >> 10, k = idx & 1023;
        g_Bx[idx] = __float2half(W[(size_t)perm_row(colp) * 2048 + 1024 + k]);
    }
    for (int idx = i0; idx < G4; idx += stride) g_bias[idx] = Wb[perm_row(idx)];
    for (int idx = i0; idx < LSEQ; idx += stride) g_bar[idx] = 0;
    for (int idx = i0; idx < NB * HID; idx += stride) g_Hbuf[0][idx] = __float2half(0.0f);
}

// ---------------- phase 1: Gx = embed(X) @ Wx^T + b ------------------------------
// CTA tile 128(m) x 128(n), K-chunk 32, 4-stage cp.async pipeline.
// 8 warps: wm 0..3 (32 rows), wn 0..1 (64 cols). 2 CTAs/SM.
#define GX_STG  4
#define GX_STR  40                               // halves per row (32 + 8 pad)
#define GX_TILE (128 * GX_STR)                   // halves per stage per matrix
#define GX_SMEM (GX_STG * 2 * GX_TILE * 2)       // bytes = 81920

__global__ __launch_bounds__(256, 2) void k_gx(const int* __restrict__ X) {
    extern __shared__ __align__(16) __half dsm[];
    __half* As = dsm;                            // [GX_STG][128][GX_STR]
    __half* Bs = dsm + GX_STG * GX_TILE;         // [GX_STG][128][GX_STR]
    __shared__ int   toks[128];
    __shared__ float bsm[128];

    int tid = threadIdx.x, lane = tid & 31, warp = tid >> 5;
    int wm = warp >> 1, wn = warp & 1;
    int mblk = blockIdx.y * 128, nblk = blockIdx.x * 128;

    if (tid < 128) {
        int m = mblk + tid;                      // m = t*64 + n
        toks[tid] = X[(m & 63) * LSEQ + (m >> 6)];
        bsm[tid] = g_bias[nblk + tid];
    }
    __syncthreads();                             // toks visible before prologue issues

    // stage loader: A,B each 128 rows x 32 halves; 2 cp16/thread per matrix
    auto issue = [&](int c) {
        __half* Ab = As + (c & (GX_STG - 1)) * GX_TILE;
        __half* Bb = Bs + (c & (GX_STG - 1)) * GX_TILE;
        int k0 = c * 32;
#pragma unroll
        for (int i = 0; i < 2; ++i) {
            int idx = tid + i * 256;             // 0..511
            int row = idx >> 2, q = idx & 3;
            cp16(Ab + row * GX_STR + q * 8,
                 &g_Eb[(size_t)toks[row] * EMBD + k0 + q * 8]);
        }
#pragma unroll
        for (int i = 0; i < 2; ++i) {
            int idx = tid + i * 256;
            int row = idx >> 2, q = idx & 3;
            cp16(Bb + row * GX_STR + q * 8,
                 &g_Bx[(size_t)(nblk + row) * 1024 + k0 + q * 8]);
        }
        cp_commit();
    };

    float acc[2][8][4];
#pragma unroll
    for (int a = 0; a < 2; ++a)
#pragma unroll
        for (int b = 0; b < 8; ++b)
#pragma unroll
            for (int c = 0; c < 4; ++c) acc[a][b][c] = 0.0f;

    issue(0); issue(1); issue(2);                // prologue: 3 stages in flight

    for (int c = 0; c < 32; ++c) {
        // wait until group c is complete (pending groups <= committed-(c+1))
        if (c < 30)       cp_wait<2>();
        else if (c == 30) cp_wait<1>();
        else              cp_wait<0>();
        __syncthreads();                         // all warps done with buf (c-1)&3 too

        if (c + 3 < 32) issue(c + 3);            // refill before compute (hides latency)

        const __half* Ab = As + (c & (GX_STG - 1)) * GX_TILE;
        const __half* Bb = Bs + (c & (GX_STG - 1)) * GX_TILE;
#pragma unroll
        for (int ks = 0; ks < 2; ++ks) {
            unsigned a[2][4];
#pragma unroll
            for (int mt = 0; mt < 2; ++mt)
                ldmatrix_x4(a[mt], smem_u32(Ab + (wm * 32 + mt * 16 + (lane & 15)) * GX_STR
                                               + ks * 16 + (lane >> 4) * 8));
#pragma unroll
            for (int nt = 0; nt < 8; ++nt) {
                unsigned b[2];
                ldmatrix_x2(b, smem_u32(Bb + (wn * 64 + nt * 8 + (lane & 7)) * GX_STR
                                           + ks * 16 + ((lane >> 3) & 1) * 8));
                mma16816(acc[0][nt], a[0], b[0], b[1]);
                mma16816(acc[1][nt], a[1], b[0], b[1]);
            }
        }
    }

    // epilogue: add bias, store permuted Gx[t][cta][n][loc]  (unchanged from R4)
#pragma unroll
    for (int mt = 0; mt < 2; ++mt) {
#pragma unroll
        for (int nt = 0; nt < 8; ++nt) {
            int mrow = mblk + wm * 32 + mt * 16 + (lane >> 2);
            int cloc = wn * 64 + nt * 8 + ((lane & 3) << 1);
            int colp = nblk + cloc;
            float b0 = bsm[cloc], b1 = bsm[cloc + 1];
            const float* c = acc[mt][nt];
#pragma unroll
            for (int rr = 0; rr < 2; ++rr) {
                int m = mrow + rr * 8;
                int t = m >> 6, n = m & 63;
                size_t off = (((size_t)t * NCTA + (colp >> 5)) * NB + n) * 32 + (colp & 31);
                float2 v; v.x = c[rr * 2] + b0; v.y = c[rr * 2 + 1] + b1;
                *(float2*)&g_Gx[off] = v;
            }
        }
    }
}

// ---------------- phase 2: persistent recurrent kernel (UNCHANGED from R4) -------
#define HS_STRIDE 1032
#define SM_HS 0
#define SM_WS (64 * HS_STRIDE * 2)                 // 132096
#define SMEM_REC (SM_WS + 32 * HS_STRIDE * 2)      // 198144

__global__ void __launch_bounds__(256, 1) k_rec(const float* __restrict__ W,
                                                float* __restrict__ out) {
    extern __shared__ __align__(16) char smem[];
    __half (*Hs)[HS_STRIDE] = (__half(*)[HS_STRIDE])(smem + SM_HS);
    __half (*Ws)[HS_STRIDE] = (__half(*)[HS_STRIDE])(smem + SM_WS);
    float* gsm = (float*)(smem + SM_HS);           // [4][64][33], aliases Hs (time-disjoint)

    int cta = blockIdx.x;
    int tid = threadIdx.x, lane = tid & 31, warp = tid >> 5;
    int wm2 = warp & 1;          // m-half: batch rows [wm2*32, +32)
    int wk  = warp >> 1;         // k-quarter: [wk*256, +256)
    int rb  = wm2 * 32;
    int cb  = wk * 256;

    for (int idx = tid; idx < 32 * 1024; idx += 256) {
        int nloc = idx >> 10, k = idx & 1023;
        int wrow = ((nloc >> 3) << 10) + (cta << 3) + (nloc & 7);
        Ws[nloc][k] = __float2half(W[(size_t)wrow * 2048 + k]);
    }
    __syncthreads();

    int em = tid >> 2, ej0 = (tid & 3) * 2;
    float C0 = 0.0f, C1 = 0.0f;
    const float* gxbase = g_Gx + (size_t)cta * NB * 32 + em * 32 + ej0;

    for (int t = 0; t < LSEQ; ++t) {
        const float* gxp = gxbase + (size_t)t * G4 * NB;
        float2 gxr[4];
#pragma unroll
        for (int g = 0; g < 4; ++g) gxr[g] = *(const float2*)(gxp + g * 8);

        const __half* Hg = g_Hbuf[t & 1];
#pragma unroll
        for (int ch = 0; ch < 2; ++ch) {
#pragma unroll
            for (int i = 0; i < 16; ++i) {
                int idx = i * 32 + lane;
                int row = rb + (idx >> 4);
                int col = cb + ch * 128 + (idx & 15) * 8;
                cp16(&Hs[row][col], Hg + row * 1024 + col);
            }
            cp_commit();
        }

        float acc[2][4][4];
#pragma unroll
        for (int a = 0; a < 2; ++a)
#pragma unroll
            for (int b = 0; b < 4; ++b)
#pragma unroll
                for (int c = 0; c < 4; ++c) acc[a][b][c] = 0.0f;

        cp_wait<1>();
        __syncwarp();
#pragma unroll
        for (int half = 0; half < 2; ++half) {
#pragma unroll 4
            for (int kt = 0; kt < 8; ++kt) {
                int k0 = cb + half * 128 + kt * 16;
                unsigned a[2][4];
#pragma unroll
                for (int mt = 0; mt < 2; ++mt)
                    ldmatrix_x4(a[mt], smem_u32(&Hs[rb + mt * 16 + (lane & 15)]
                                                  [k0 + (lane >> 4) * 8]));
#pragma unroll
                for (int bg = 0; bg < 2; ++bg) {
                    unsigned b[4];
                    ldmatrix_x4(b, smem_u32(&Ws[bg * 16 + ((lane >> 4) << 3) + (lane & 7)]
                                              [k0 + ((lane >> 3) & 1) * 8]));
#pragma unroll
                    for (int mt = 0; mt < 2; ++mt) {
                        mma16816(acc[mt][bg * 2],     a[mt], b[0], b[1]);
                        mma16816(acc[mt][bg * 2 + 1], a[mt], b[2], b[3]);
                    }
                }
            }
            if (half == 0) { cp_wait<0>(); __syncwarp(); }
        }

        __syncthreads();
        {
            float* gp = gsm + wk * (64 * 33);
            int mrow = rb + (lane >> 2);
            int ncol = (lane & 3) << 1;
#pragma unroll
            for (int mt = 0; mt < 2; ++mt)
#pragma unroll
                for (int ng = 0; ng < 4; ++ng) {
                    const float* c = acc[mt][ng];
                    int m = mrow + mt * 16, n = ng * 8 + ncol;
                    gp[m * 33 + n]           = c[0];
                    gp[m * 33 + n + 1]       = c[1];
                    gp[(m + 8) * 33 + n]     = c[2];
                    gp[(m + 8) * 33 + n + 1] = c[3];
                }
        }
        __syncthreads();

        float s[4][2];
#pragma unroll
        for (int g = 0; g < 4; ++g) {
            float v0 = gxr[g].x, v1 = gxr[g].y;
            int base = em * 33 + g * 8 + ej0;
#pragma unroll
            for (int q = 0; q < 4; ++q) {
                v0 += gsm[q * (64 * 33) + base];
                v1 += gsm[q * (64 * 33) + base + 1];
            }
            s[g][0] = v0; s[g][1] = v1;
        }
        float i0 = sigf(s[0][0]), f0 = sigf(s[1][0]), o0 = sigf(s[2][0]), g0 = tanhf(s[3][0]);
        float i1 = sigf(s[0][1]), f1 = sigf(s[1][1]), o1 = sigf(s[2][1]), g1 = tanhf(s[3][1]);
        C0 = f0 * C0 + i0 * g0;
        C1 = f1 * C1 + i1 * g1;
        float h0 = o0 * tanhf(C0), h1 = o1 * tanhf(C1);

        __half* Hn = g_Hbuf[(t & 1) ^ 1];
        int hcol = (cta << 3) + ej0;
        *(__half2*)(Hn + em * 1024 + hcol) = __floats2half2_rn(h0, h1);
        if (t == LSEQ - 1) {
            float2 ov; ov.x = h0; ov.y = h1;
            *(float2*)(out + em * 1024 + hcol) = ov;
        }

        __threadfence();
        __syncthreads();
        if (tid == 0) {
            atomicAdd(&g_bar[t], 1);
            while (*(volatile int*)&g_bar[t] < NCTA) { }
        }
        __syncthreads();
    }
}

// ---------------- launch ----------------------------------------------------------
extern "C" void kernel_launch(void* const* d_in, const int* in_sizes, int n_in,
                              void* d_out, int out_size) {
    (void)in_sizes; (void)n_in; (void)out_size;
    const int*   X  = (const int*)d_in[0];
    const float* E  = (const float*)d_in[1];
    const float* W  = (const float*)d_in[2];
    const float* Wb = (const float*)d_in[3];
    float* out = (float*)d_out;

    cudaFuncSetAttribute(k_rec, cudaFuncAttributeMaxDynamicSharedMemorySize, SMEM_REC);
    cudaFuncSetAttribute(k_gx, cudaFuncAttributeMaxDynamicSharedMemorySize, GX_SMEM);

    k_cvt_e<<<2048, 256>>>(E);
    k_pack<<<1024, 256>>>(W, Wb);
    k_gx<<<dim3(32, 256), 256, GX_SMEM>>>(X);
    k_rec<<<NCTA, 256, SMEM_REC>>>(W, out);
}